// round 16
// baseline (speedup 1.0000x reference)
#include <cuda_runtime.h>
#include <cstdint>

#define COLS    24576
#define TPB     512
#define NWARP   (TPB / 32)          // 16
#define VPT     (COLS / (TPB * 4))  // 12 float4 per thread
#define TCAP    6                   // per-thread candidate slots
#define CANDCAP 1024

__device__ __forceinline__ unsigned sortable_u(unsigned b) {
    return b ^ ((unsigned)((int)b >> 31) | 0x80000000u);
}

__global__ __launch_bounds__(TPB, 2) void topk_mask_kernel(
    const float* __restrict__ x, const int* __restrict__ kptr, float* __restrict__ out)
{
    __shared__ unsigned long long tseg[TPB * TCAP];     // 24 KB: per-thread segments
    __shared__ unsigned long long candKey[CANDCAP];     //  8 KB
    __shared__ int wsum[NWARP];
    __shared__ int red[NWARP];
    __shared__ int sh_m;
    __shared__ int sh_fail;
    __shared__ int sh_tot;
    __shared__ unsigned sh_ucut;
    __shared__ int sh_icut;

    const int tid  = threadIdx.x;
    const int lane = tid & 31;
    const int warp = tid >> 5;
    const size_t rbase = (size_t)blockIdx.x * COLS;
    const float4* rx = reinterpret_cast<const float4*>(x + rbase);
    float4*       ro = reinterpret_cast<float4*>(out + rbase);

    int k = kptr ? kptr[0] : 64;
    k = max(1, min(k, COLS));

    if (tid == 0) sh_fail = 0;

    // ---- Pass 1: stream row; per-thread private collect (no warp comm) ------
    // Each thread appends hits to its own TCAP-slot shared segment with a
    // register counter: compare + predicated STS only. Loads have no
    // dependent warp-wide ops, so ptxas can front-batch them freely.
    const float THR = 2.5f;   // E[#cand] ~ 153/row; per-thread lambda ~ 0.3
    int cnt = 0;
    #pragma unroll
    for (int i = 0; i < VPT; i++) {
        const int v4 = tid + i * TPB;
        const float4 f = rx[v4];
        const int base = v4 * 4;
        const float vals[4] = {f.x, f.y, f.z, f.w};
        #pragma unroll
        for (int j = 0; j < 4; j++) {
            if (vals[j] >= THR) {
                if (cnt < TCAP) {
                    const unsigned u = __float_as_uint(vals[j]) | 0x80000000u; // >0
                    // value-descending, index-ascending (stable top_k order)
                    tseg[tid * TCAP + cnt] =
                        ((unsigned long long)u << 15) | (unsigned)(0x7FFF - (base + j));
                }
                cnt++;
            }
        }
    }
    if (cnt > TCAP) sh_fail = 1;    // benign race: any writer sets 1

    // ---- Zero-fill output row (independent stores; drain during ranking) ----
    const float4 z4 = make_float4(0.f, 0.f, 0.f, 0.f);
    #pragma unroll
    for (int i = 0; i < VPT; i++)
        __stcs(ro + tid + i * TPB, z4);

    // ---- Block-wide exclusive scan of per-thread counts ----------------------
    const int myc = min(cnt, TCAP);
    int s = myc;
    #pragma unroll
    for (int d = 1; d < 32; d <<= 1) {
        const int t = __shfl_up_sync(0xffffffffu, s, d);
        if (lane >= d) s += t;
    }
    if (lane == 31) wsum[warp] = s;
    __syncthreads();
    if (warp == 0) {
        int c = (lane < NWARP) ? wsum[lane] : 0;
        int ss = c;
        #pragma unroll
        for (int d = 1; d < 32; d <<= 1) {
            const int t = __shfl_up_sync(0xffffffffu, ss, d);
            if (lane >= d) ss += t;
        }
        if (lane < NWARP) wsum[lane] = ss - c;    // exclusive warp offsets
        if (lane == NWARP - 1) sh_m = ss;
    }
    __syncthreads();

    const int m = sh_m;
    const bool fail = (sh_fail != 0) || (m < k) || (m > CANDCAP);  // block-uniform

    if (!fail) {
        // compact per-thread segments into contiguous candKey
        {
            const int off = wsum[warp] + (s - myc);   // block-exclusive offset
            for (int j = 0; j < myc; j++)
                candKey[off + j] = tseg[tid * TCAP + j];
        }
        __syncthreads();
        // rank-by-count over ~153 unique keys; winners scatter directly
        for (int j = tid; j < m; j += TPB) {
            const unsigned long long kj = candKey[j];
            int r = 0;
            for (int i = 0; i < m; i++) r += (candKey[i] > kj) ? 1 : 0;
            if (r < k) {
                const int idx = 0x7FFF - (int)(kj & 0x7FFFull);
                out[rbase + idx] =
                    __uint_as_float((unsigned)(kj >> 15) & 0x7FFFFFFFu);
            }
        }
        return;
    }

    // ---------------- exact fallback (any data): bisection + scatter ---------
    {
        auto blockSum = [&](int c) -> int {
            #pragma unroll
            for (int d = 16; d; d >>= 1) c += __shfl_down_sync(0xffffffffu, c, d);
            __syncthreads();
            if (lane == 0) red[warp] = c;
            __syncthreads();
            if (tid == 0) {
                int t = 0;
                for (int w = 0; w < NWARP; w++) t += red[w];
                sh_tot = t;
            }
            __syncthreads();
            return sh_tot;
        };
        auto countGE = [&](unsigned v) -> int {
            int c = 0;
            for (int i = 0; i < VPT; i++) {
                const float4 f = rx[tid + i * TPB];
                c += (sortable_u(__float_as_uint(f.x)) >= v);
                c += (sortable_u(__float_as_uint(f.y)) >= v);
                c += (sortable_u(__float_as_uint(f.z)) >= v);
                c += (sortable_u(__float_as_uint(f.w)) >= v);
            }
            return blockSum(c);
        };
        auto countEQLE = [&](unsigned v, int idxle) -> int {
            int c = 0;
            for (int i = 0; i < VPT; i++) {
                const int v4 = tid + i * TPB;
                const float4 f = rx[v4];
                const int base = v4 * 4;
                c += (sortable_u(__float_as_uint(f.x)) == v && base + 0 <= idxle);
                c += (sortable_u(__float_as_uint(f.y)) == v && base + 1 <= idxle);
                c += (sortable_u(__float_as_uint(f.z)) == v && base + 2 <= idxle);
                c += (sortable_u(__float_as_uint(f.w)) == v && base + 3 <= idxle);
            }
            return blockSum(c);
        };

        unsigned lo = 0u, hi = 0xFFFFFFFFu;      // max v with countGE(v) >= k
        while (lo < hi) {
            const unsigned mid = lo + ((hi - lo) >> 1) + 1u;
            if (countGE(mid) >= k) lo = mid; else hi = mid - 1u;
        }
        const unsigned ucut = lo;
        const int cgt  = (ucut == 0xFFFFFFFFu) ? 0 : countGE(ucut + 1u);
        const int need = k - cgt;
        int l2 = 0, h2 = COLS - 1;               // smallest idx with countEQLE >= need
        while (l2 < h2) {
            const int mid = (l2 + h2) >> 1;
            if (countEQLE(ucut, mid) >= need) h2 = mid; else l2 = mid + 1;
        }
        if (tid == 0) { sh_ucut = ucut; sh_icut = l2; }
        __syncthreads();

        const unsigned ucut2 = sh_ucut;
        const int      icut2 = sh_icut;
        // scatter winners over the zero-filled row (reads hit L2)
        for (int i = 0; i < VPT; i++) {
            const int v4 = tid + i * TPB;
            const float4 f = __ldcs(rx + v4);
            const int base = v4 * 4;
            const float vals[4] = {f.x, f.y, f.z, f.w};
            #pragma unroll
            for (int j = 0; j < 4; j++) {
                const unsigned u = sortable_u(__float_as_uint(vals[j]));
                if (u > ucut2 || (u == ucut2 && base + j <= icut2))
                    out[rbase + base + j] = vals[j];
            }
        }
    }
}

extern "C" void kernel_launch(void* const* d_in, const int* in_sizes, int n_in,
                              void* d_out, int out_size)
{
    const float* x  = (const float*)d_in[0];
    const int*   kp = (n_in >= 2) ? (const int*)d_in[1] : nullptr;
    const int rows = in_sizes[0] / COLS;
    if (rows <= 0) return;
    topk_mask_kernel<<<rows, TPB>>>(x, kp, (float*)d_out);
}

// round 17
// speedup vs baseline: 1.2158x; 1.2158x over previous
#include <cuda_runtime.h>
#include <cstdint>

#define COLS    24576
#define TPB     512
#define NWARP   (TPB / 32)          // 16
#define VPT     (COLS / (TPB * 4))  // 12 float4 per thread (48 elements)
#define CANDCAP 1024

__device__ __forceinline__ unsigned sortable_u(unsigned b) {
    return b ^ ((unsigned)((int)b >> 31) | 0x80000000u);
}

__global__ __launch_bounds__(TPB, 2) void topk_mask_kernel(
    const float* __restrict__ x, const int* __restrict__ kptr, float* __restrict__ out)
{
    __shared__ unsigned long long candKey[CANDCAP];
    __shared__ int sh_nc;
    __shared__ int red[NWARP];
    __shared__ int sh_tot;
    __shared__ unsigned sh_ucut;
    __shared__ int sh_icut;

    const int tid  = threadIdx.x;
    const int lane = tid & 31;
    const int warp = tid >> 5;
    const size_t rbase = (size_t)blockIdx.x * COLS;
    const float4* rx = reinterpret_cast<const float4*>(x + rbase);
    float4*       ro = reinterpret_cast<float4*>(out + rbase);

    int k = kptr ? kptr[0] : 64;
    k = max(1, min(k, COLS));

    if (tid == 0) sh_nc = 0;
    __syncthreads();                 // sh_nc=0 visible before any extraction atomics

    // ---- Pass 1: pure stream — loads + compares + branch-free mask build ----
    // No ballot, no shared store, no divergent branch in the loop: each
    // element contributes one bit to a per-thread 48-bit register mask.
    // Value liveness is load->compare, so ptxas can pipeline loads deeply.
    const float THR = 2.5f;   // E[#cand] ~ 153/row; P(row < 64 cands) ~ 3e-13
    unsigned long long mask = 0ull;
    #pragma unroll
    for (int i = 0; i < VPT; i++) {
        const float4 f = rx[tid + i * TPB];
        const unsigned nib = (unsigned)(f.x >= THR)
                           | ((unsigned)(f.y >= THR) << 1)
                           | ((unsigned)(f.z >= THR) << 2)
                           | ((unsigned)(f.w >= THR) << 3);
        mask |= (unsigned long long)nib << (4 * i);
    }

    // ---- Zero-fill output row (independent stores; drain during extraction) -
    const float4 z4 = make_float4(0.f, 0.f, 0.f, 0.f);
    #pragma unroll
    for (int i = 0; i < VPT; i++)
        __stcs(ro + tid + i * TPB, z4);

    // ---- Extraction: walk set bits (avg 0.3/thread), re-load (L1/L2 hit), ---
    // ---- append via shared atomic (~153 total per block, off the hot loop) --
    while (mask) {
        const int b = __ffsll((long long)mask) - 1;
        mask &= mask - 1ull;
        const int i = b >> 2, j = b & 3;
        const int idx = (tid + i * TPB) * 4 + j;
        const float v = __ldg(x + rbase + idx);
        const int slot = atomicAdd(&sh_nc, 1);
        if (slot < CANDCAP) {
            const unsigned u = __float_as_uint(v) | 0x80000000u;  // v > 0 here
            // value-descending, index-ascending (stable top_k order)
            candKey[slot] = ((unsigned long long)u << 15)
                            | (unsigned)(0x7FFF - idx);
        }
    }
    __syncthreads();   // candKey complete; zero stores ordered before scatter

    const int  m    = min(sh_nc, CANDCAP);
    const bool fail = (sh_nc > CANDCAP) || (m < k);   // block-uniform

    if (!fail) {
        // rank-by-count over ~153 unique keys; winners scatter directly
        for (int j = tid; j < m; j += TPB) {
            const unsigned long long kj = candKey[j];
            int r = 0;
            for (int i = 0; i < m; i++) r += (candKey[i] > kj) ? 1 : 0;
            if (r < k) {
                const int idx = 0x7FFF - (int)(kj & 0x7FFFull);
                out[rbase + idx] =
                    __uint_as_float((unsigned)(kj >> 15) & 0x7FFFFFFFu);
            }
        }
        return;
    }

    // ---------------- exact fallback (any data): bisection + scatter ---------
    {
        auto blockSum = [&](int c) -> int {
            #pragma unroll
            for (int d = 16; d; d >>= 1) c += __shfl_down_sync(0xffffffffu, c, d);
            __syncthreads();
            if (lane == 0) red[warp] = c;
            __syncthreads();
            if (tid == 0) {
                int t = 0;
                for (int w = 0; w < NWARP; w++) t += red[w];
                sh_tot = t;
            }
            __syncthreads();
            return sh_tot;
        };
        auto countGE = [&](unsigned v) -> int {
            int c = 0;
            for (int i = 0; i < VPT; i++) {
                const float4 f = rx[tid + i * TPB];
                c += (sortable_u(__float_as_uint(f.x)) >= v);
                c += (sortable_u(__float_as_uint(f.y)) >= v);
                c += (sortable_u(__float_as_uint(f.z)) >= v);
                c += (sortable_u(__float_as_uint(f.w)) >= v);
            }
            return blockSum(c);
        };
        auto countEQLE = [&](unsigned v, int idxle) -> int {
            int c = 0;
            for (int i = 0; i < VPT; i++) {
                const int v4 = tid + i * TPB;
                const float4 f = rx[v4];
                const int base = v4 * 4;
                c += (sortable_u(__float_as_uint(f.x)) == v && base + 0 <= idxle);
                c += (sortable_u(__float_as_uint(f.y)) == v && base + 1 <= idxle);
                c += (sortable_u(__float_as_uint(f.z)) == v && base + 2 <= idxle);
                c += (sortable_u(__float_as_uint(f.w)) == v && base + 3 <= idxle);
            }
            return blockSum(c);
        };

        unsigned lo = 0u, hi = 0xFFFFFFFFu;      // max v with countGE(v) >= k
        while (lo < hi) {
            const unsigned mid = lo + ((hi - lo) >> 1) + 1u;
            if (countGE(mid) >= k) lo = mid; else hi = mid - 1u;
        }
        const unsigned ucut = lo;
        const int cgt  = (ucut == 0xFFFFFFFFu) ? 0 : countGE(ucut + 1u);
        const int need = k - cgt;
        int l2 = 0, h2 = COLS - 1;               // smallest idx with countEQLE >= need
        while (l2 < h2) {
            const int mid = (l2 + h2) >> 1;
            if (countEQLE(ucut, mid) >= need) h2 = mid; else l2 = mid + 1;
        }
        if (tid == 0) { sh_ucut = ucut; sh_icut = l2; }
        __syncthreads();

        const unsigned ucut2 = sh_ucut;
        const int      icut2 = sh_icut;
        // scatter winners over the zero-filled row (reads hit L2)
        for (int i = 0; i < VPT; i++) {
            const int v4 = tid + i * TPB;
            const float4 f = __ldcs(rx + v4);
            const int base = v4 * 4;
            const float vals[4] = {f.x, f.y, f.z, f.w};
            #pragma unroll
            for (int j = 0; j < 4; j++) {
                const unsigned u = sortable_u(__float_as_uint(vals[j]));
                if (u > ucut2 || (u == ucut2 && base + j <= icut2))
                    out[rbase + base + j] = vals[j];
            }
        }
    }
}

extern "C" void kernel_launch(void* const* d_in, const int* in_sizes, int n_in,
                              void* d_out, int out_size)
{
    const float* x  = (const float*)d_in[0];
    const int*   kp = (n_in >= 2) ? (const int*)d_in[1] : nullptr;
    const int rows = in_sizes[0] / COLS;
    if (rows <= 0) return;
    topk_mask_kernel<<<rows, TPB>>>(x, kp, (float*)d_out);
}